// round 3
// baseline (speedup 1.0000x reference)
#include <cuda_runtime.h>
#include <math.h>

// Problem constants
#define BB 4
#define TT 4096
#define DD 1024
#define HH 16
#define HD 64
#define TS 1024            // strided sequence length (TT / 4)
#define MROWS (BB*TS)      // 4096 GEMM rows

// Scratch (allocation-free: __device__ globals)
__device__ float g_xs[BB*TS*DD];          // 16 MB  LN'd strided rows
__device__ float g_qkv[BB*TS*3*DD];       // 48 MB  qkv
__device__ float g_attn[BB*TS*DD];        // 16 MB  attention output (B,Ts,D)
__device__ float g_proj[BB*TS*DD];        // 16 MB  out projection

// ---------------------------------------------------------------------------
// LayerNorm on strided rows only: x[b, 4*ts, :] -> g_xs[b*TS+ts, :]
// ---------------------------------------------------------------------------
__global__ __launch_bounds__(256) void ln_kernel(const float* __restrict__ x,
                                                 const float* __restrict__ w,
                                                 const float* __restrict__ bias)
{
    int row = blockIdx.x;            // 0..4095 = b*TS + ts
    int b = row >> 10, ts = row & 1023;
    int tid = threadIdx.x;
    const float4* xr = (const float4*)(x + ((size_t)(b*TT + ts*4))*DD);
    float4 v = xr[tid];
    float s  = v.x + v.y + v.z + v.w;
    float sq = v.x*v.x + v.y*v.y + v.z*v.z + v.w*v.w;
    #pragma unroll
    for (int o = 16; o > 0; o >>= 1) {
        s  += __shfl_xor_sync(0xffffffffu, s,  o);
        sq += __shfl_xor_sync(0xffffffffu, sq, o);
    }
    __shared__ float rs[8], rq[8];
    int wid = tid >> 5, lane = tid & 31;
    if (lane == 0) { rs[wid] = s; rq[wid] = sq; }
    __syncthreads();
    if (tid == 0) {
        float S = 0.f, Q = 0.f;
        #pragma unroll
        for (int i = 0; i < 8; i++) { S += rs[i]; Q += rq[i]; }
        rs[0] = S; rq[0] = Q;
    }
    __syncthreads();
    float mean = rs[0] * (1.0f/DD);
    float var  = rq[0] * (1.0f/DD) - mean*mean;
    float rstd = rsqrtf(var + 1e-5f);
    float4 wv = ((const float4*)w)[tid];
    float4 bv = ((const float4*)bias)[tid];
    float4 o;
    o.x = (v.x - mean)*rstd*wv.x + bv.x;
    o.y = (v.y - mean)*rstd*wv.y + bv.y;
    o.z = (v.z - mean)*rstd*wv.z + bv.z;
    o.w = (v.w - mean)*rstd*wv.w + bv.w;
    ((float4*)(g_xs + (size_t)row*DD))[tid] = o;
}

// ---------------------------------------------------------------------------
// Double-buffered 128x128x8 register-tiled fp32 GEMM:
//   C = A[M,K] @ B[K,N] + bias[N]
// 256 threads, 8x8 microtile per thread, one __syncthreads per K-step.
// ---------------------------------------------------------------------------
__global__ __launch_bounds__(256) void sgemm128(const float* __restrict__ A,
                                                const float* __restrict__ Bm,
                                                const float* __restrict__ bias,
                                                float* __restrict__ C,
                                                int M, int N, int K)
{
    __shared__ float As[2][8][128];
    __shared__ float Bs[2][8][128];
    int tid = threadIdx.x;
    int bm = blockIdx.y * 128, bn = blockIdx.x * 128;

    int a_row = tid >> 1;            // 0..127
    int a_k   = (tid & 1) * 4;       // 0 or 4
    int b_k   = tid >> 5;            // 0..7
    int b_n   = (tid & 31) * 4;      // 0..124
    int tx = (tid & 15) * 8;
    int ty = (tid >> 4) * 8;

    float acc[8][8];
    #pragma unroll
    for (int i = 0; i < 8; i++)
        #pragma unroll
        for (int j = 0; j < 8; j++) acc[i][j] = 0.f;

    const float* Aptr = A + (size_t)(bm + a_row)*K + a_k;
    const float* Bptr = Bm + (size_t)b_k*N + bn + b_n;

    // Prologue: load tile 0 into buffer 0
    {
        float4 av = *(const float4*)(Aptr);
        float4 bv = *(const float4*)(Bptr);
        As[0][a_k+0][a_row] = av.x; As[0][a_k+1][a_row] = av.y;
        As[0][a_k+2][a_row] = av.z; As[0][a_k+3][a_row] = av.w;
        *(float4*)&Bs[0][b_k][b_n] = bv;
    }
    __syncthreads();

    int buf = 0;
    for (int k0 = 0; k0 < K; k0 += 8, buf ^= 1) {
        // Prefetch next tile into registers (overlaps with compute below)
        float4 av, bv;
        bool has_next = (k0 + 8) < K;
        if (has_next) {
            av = *(const float4*)(Aptr + k0 + 8);
            bv = *(const float4*)(Bptr + (size_t)(k0 + 8)*N);
        }

        // Compute on current buffer
        #pragma unroll
        for (int kk = 0; kk < 8; kk++) {
            float af[8], bf[8];
            #pragma unroll
            for (int i = 0; i < 8; i++) af[i] = As[buf][kk][ty+i];
            #pragma unroll
            for (int j = 0; j < 8; j++) bf[j] = Bs[buf][kk][tx+j];
            #pragma unroll
            for (int i = 0; i < 8; i++)
                #pragma unroll
                for (int j = 0; j < 8; j++)
                    acc[i][j] = fmaf(af[i], bf[j], acc[i][j]);
        }

        // Stage next tile into the alternate buffer
        if (has_next) {
            int nb = buf ^ 1;
            As[nb][a_k+0][a_row] = av.x; As[nb][a_k+1][a_row] = av.y;
            As[nb][a_k+2][a_row] = av.z; As[nb][a_k+3][a_row] = av.w;
            *(float4*)&Bs[nb][b_k][b_n] = bv;
            __syncthreads();
        }
    }

    #pragma unroll
    for (int i = 0; i < 8; i++) {
        float* crow = C + (size_t)(bm+ty+i)*N + bn + tx;
        #pragma unroll
        for (int j = 0; j < 8; j += 4) {
            float4 o;
            o.x = acc[i][j+0] + bias[bn+tx+j+0];
            o.y = acc[i][j+1] + bias[bn+tx+j+1];
            o.z = acc[i][j+2] + bias[bn+tx+j+2];
            o.w = acc[i][j+3] + bias[bn+tx+j+3];
            *(float4*)(crow + j) = o;
        }
    }
}

// ---------------------------------------------------------------------------
// RoPE in-place on q,k parts of g_qkv.  angle(t, i) = t / 10000^(2i/64)
// q'[i] = q[i]*c - q[i+32]*s ; q'[i+32] = q[i+32]*c + q[i]*s
// ---------------------------------------------------------------------------
__global__ __launch_bounds__(256) void rope_kernel()
{
    int idx = blockIdx.x * 256 + threadIdx.x;   // 2^21 total
    int i  = idx & 31;
    int h  = (idx >> 5) & 15;
    int ts = (idx >> 9) & 1023;
    int b  = idx >> 19;
    float freq = expf(-(float)(2*i) * (9.210340371976184f / 64.0f)); // 1/10000^(2i/64)
    float ang = (float)ts * freq;
    float sn, cs;
    sincosf(ang, &sn, &cs);
    int base = (b*TS + ts)*3*DD + h*HD;
    float q0 = g_qkv[base+i], q1 = g_qkv[base+i+32];
    g_qkv[base+i]    = q0*cs - q1*sn;
    g_qkv[base+i+32] = q1*cs + q0*sn;
    base += DD;
    float k0 = g_qkv[base+i], k1 = g_qkv[base+i+32];
    g_qkv[base+i]    = k0*cs - k1*sn;
    g_qkv[base+i+32] = k1*cs + k0*sn;
}

// ---------------------------------------------------------------------------
// Causal flash attention.  One CTA per (q-block of 64, b*h). 128 threads.
// BN = 32 keys per tile.  Online softmax, fp32 throughout.
// ---------------------------------------------------------------------------
__global__ __launch_bounds__(128) void attn_kernel()
{
    __shared__ float Qts[64][65];   // transposed Q tile (scaled by 1/8)
    __shared__ float Kts[64][33];   // transposed K tile
    __shared__ float Vs[32][64];
    __shared__ float Ss[64][33];    // probabilities
    __shared__ float row_m[64], row_l[64], row_a[64];

    int tid  = threadIdx.x;
    int qblk = blockIdx.x;          // 0..15
    int bh   = blockIdx.y;          // 0..63
    int b = bh >> 4, h = bh & 15;

    // Load + transpose Q tile (64 rows x 64 dims), fold 1/sqrt(hd)=0.125
    const float* qbase = g_qkv + (size_t)(b*TS + qblk*64)*3*DD + h*HD;
    int ld_m = tid >> 4;            // 0..7 (plus 8*r)
    int ld_c = (tid & 15) * 4;      // 0..60
    #pragma unroll
    for (int r = 0; r < 8; r++) {
        int m = ld_m + 8*r;
        float4 v = *(const float4*)(qbase + (size_t)m*3*DD + ld_c);
        Qts[ld_c+0][m] = v.x*0.125f; Qts[ld_c+1][m] = v.y*0.125f;
        Qts[ld_c+2][m] = v.z*0.125f; Qts[ld_c+3][m] = v.w*0.125f;
    }
    if (tid < 64) { row_m[tid] = -1e30f; row_l[tid] = 0.f; }

    float o[4][8];
    #pragma unroll
    for (int i = 0; i < 4; i++)
        #pragma unroll
        for (int j = 0; j < 8; j++) o[i][j] = 0.f;

    int sy = tid >> 2;           // score phase: rows 2*sy, 2*sy+1
    int sx = (tid & 3) * 8;      //              cols sx..sx+7
    int py = tid >> 3;           // PV phase:    rows 4*py..+3
    int px = (tid & 7) * 8;      //              dims px..px+7

    int nkt = 2*qblk + 2;        // causal: tiles of 32 keys
    for (int kt = 0; kt < nkt; kt++) {
        const float* kb = g_qkv + (size_t)(b*TS + kt*32)*3*DD + DD + h*HD
                        + (size_t)(tid >> 4)*3*DD + ld_c;
        float4 kv4[4], vv4[4];
        #pragma unroll
        for (int r = 0; r < 4; r++) {
            kv4[r] = *(const float4*)(kb + (size_t)(8*r)*3*DD);
            vv4[r] = *(const float4*)(kb + (size_t)(8*r)*3*DD + DD);
        }
        __syncthreads();         // previous PV done reading Vs/Ss
        #pragma unroll
        for (int r = 0; r < 4; r++) {
            int n = (tid >> 4) + 8*r;
            Kts[ld_c+0][n] = kv4[r].x; Kts[ld_c+1][n] = kv4[r].y;
            Kts[ld_c+2][n] = kv4[r].z; Kts[ld_c+3][n] = kv4[r].w;
            *(float4*)&Vs[n][ld_c] = vv4[r];
        }
        __syncthreads();

        // --- scores: s[2][8] = (Q/8) @ K^T over d=64 ---
        float s[2][8];
        #pragma unroll
        for (int j = 0; j < 8; j++) { s[0][j] = 0.f; s[1][j] = 0.f; }
        #pragma unroll 8
        for (int d = 0; d < 64; d++) {
            float q0 = Qts[d][2*sy], q1 = Qts[d][2*sy+1];
            #pragma unroll
            for (int j = 0; j < 8; j++) {
                float kvv = Kts[d][sx+j];
                s[0][j] = fmaf(q0, kvv, s[0][j]);
                s[1][j] = fmaf(q1, kvv, s[1][j]);
            }
        }

        // --- mask + online softmax (row spread over 4 lanes) ---
        #pragma unroll
        for (int i = 0; i < 2; i++) {
            int rr = 2*sy + i;
            int qrow = qblk*64 + rr;
            float mx = -1e30f;
            #pragma unroll
            for (int j = 0; j < 8; j++) {
                int kc = kt*32 + sx + j;
                if (kc > qrow) s[i][j] = -1e30f;
                mx = fmaxf(mx, s[i][j]);
            }
            mx = fmaxf(mx, __shfl_xor_sync(0xffffffffu, mx, 1));
            mx = fmaxf(mx, __shfl_xor_sync(0xffffffffu, mx, 2));
            float mo = row_m[rr];
            float mn = fmaxf(mo, mx);
            float al = __expf(mo - mn);
            float sum = 0.f;
            #pragma unroll
            for (int j = 0; j < 8; j++) {
                float p = __expf(s[i][j] - mn);
                s[i][j] = p;
                sum += p;
            }
            sum += __shfl_xor_sync(0xffffffffu, sum, 1);
            sum += __shfl_xor_sync(0xffffffffu, sum, 2);
            if ((tid & 3) == 0) {
                row_m[rr] = mn;
                row_a[rr] = al;
                row_l[rr] = row_l[rr]*al + sum;
            }
            #pragma unroll
            for (int j = 0; j < 8; j++) Ss[rr][sx+j] = s[i][j];
        }
        __syncthreads();

        // --- PV: o[4][8] = o*alpha + P @ V ---
        #pragma unroll
        for (int i = 0; i < 4; i++) {
            float al = row_a[py*4 + i];
            #pragma unroll
            for (int j = 0; j < 8; j++) o[i][j] *= al;
        }
        #pragma unroll 8
        for (int n = 0; n < 32; n++) {
            float pv[4];
            #pragma unroll
            for (int i = 0; i < 4; i++) pv[i] = Ss[py*4+i][n];
            #pragma unroll
            for (int j = 0; j < 8; j++) {
                float vvv = Vs[n][px+j];
                #pragma unroll
                for (int i = 0; i < 4; i++)
                    o[i][j] = fmaf(pv[i], vvv, o[i][j]);
            }
        }
    }
    __syncthreads();

    // Finalize: divide by l, write [B, Ts, D] with d = h*64 + px..
    #pragma unroll
    for (int i = 0; i < 4; i++) {
        int m = py*4 + i;
        float inv = 1.0f / row_l[m];
        float* orow = g_attn + (size_t)(b*TS + qblk*64 + m)*DD + h*HD + px;
        #pragma unroll
        for (int j = 0; j < 8; j += 4) {
            float4 ov;
            ov.x = o[i][j+0]*inv; ov.y = o[i][j+1]*inv;
            ov.z = o[i][j+2]*inv; ov.w = o[i][j+3]*inv;
            *(float4*)(orow + j) = ov;
        }
    }
}

// ---------------------------------------------------------------------------
// Linear upsample Ts->T (scale 0.25) + residual add.
// ---------------------------------------------------------------------------
__global__ __launch_bounds__(256) void upsample_kernel(const float* __restrict__ x,
                                                       float* __restrict__ outp)
{
    int gid = blockIdx.x * 256 + threadIdx.x;   // float4 index, 4.19M total
    int d4 = gid & 255;                         // 256 float4 per D row
    int t  = (gid >> 8) & (TT - 1);
    int b  = gid >> 20;
    float src = ((float)t + 0.5f) * ((float)TS / (float)TT) - 0.5f;
    src = fminf(fmaxf(src, 0.0f), (float)(TS - 1));
    float fi0 = floorf(src);
    int i0 = (int)fi0;
    int i1 = min(i0 + 1, TS - 1);
    float w  = src - fi0;
    float w0 = 1.0f - w;
    const float4* pr = (const float4*)g_proj;
    float4 p0 = pr[(b*TS + i0)*256 + d4];
    float4 p1 = pr[(b*TS + i1)*256 + d4];
    float4 xv = ((const float4*)x)[gid];
    float4 ov;
    ov.x = xv.x + p0.x*w0 + p1.x*w;
    ov.y = xv.y + p0.y*w0 + p1.y*w;
    ov.z = xv.z + p0.z*w0 + p1.z*w;
    ov.w = xv.w + p0.w*w0 + p1.w*w;
    ((float4*)outp)[gid] = ov;
}

// ---------------------------------------------------------------------------
extern "C" void kernel_launch(void* const* d_in, const int* in_sizes, int n_in,
                              void* d_out, int out_size)
{
    const float* x      = (const float*)d_in[0];
    const float* norm_w = (const float*)d_in[1];
    const float* norm_b = (const float*)d_in[2];
    const float* W_qkv  = (const float*)d_in[3];
    const float* b_qkv  = (const float*)d_in[4];
    const float* W_out  = (const float*)d_in[5];
    const float* b_out  = (const float*)d_in[6];
    float* out = (float*)d_out;

    float *xs_p, *qkv_p, *attn_p, *proj_p;
    cudaGetSymbolAddress((void**)&xs_p,   g_xs);
    cudaGetSymbolAddress((void**)&qkv_p,  g_qkv);
    cudaGetSymbolAddress((void**)&attn_p, g_attn);
    cudaGetSymbolAddress((void**)&proj_p, g_proj);

    ln_kernel<<<BB*TS, 256>>>(x, norm_w, norm_b);

    sgemm128<<<dim3(3*DD/128, MROWS/128), 256>>>(xs_p, W_qkv, b_qkv, qkv_p,
                                                 MROWS, 3*DD, DD);

    rope_kernel<<<(BB*TS*HH*32)/256, 256>>>();

    attn_kernel<<<dim3(TS/64, BB*HH), 128>>>();

    sgemm128<<<dim3(DD/128, MROWS/128), 256>>>(attn_p, W_out, b_out, proj_p,
                                               MROWS, DD, DD);

    upsample_kernel<<<(BB*TT*DD/4)/256, 256>>>(x, out);
}

// round 10
// speedup vs baseline: 1.4973x; 1.4973x over previous
#include <cuda_runtime.h>
#include <cuda_bf16.h>
#include <math.h>
#include <stdint.h>

// Problem constants
#define BB 4
#define TT 4096
#define DD 1024
#define HH 16
#define HD 64
#define TS 1024            // strided sequence length (TT / 4)
#define MROWS (BB*TS)      // 4096 GEMM rows

// Scratch (allocation-free: __device__ globals)
__device__ float g_qkv[MROWS*3*DD];                     // 48 MB qkv fp32
__device__ float g_proj[MROWS*DD];                      // 16 MB out projection
__device__ __nv_bfloat16 g_a1h[MROWS*DD], g_a1l[MROWS*DD];   // LN rows, split bf16
__device__ __nv_bfloat16 g_a2h[MROWS*DD], g_a2l[MROWS*DD];   // attn out, split bf16
__device__ __nv_bfloat16 g_wqh[3*DD*DD], g_wql[3*DD*DD];     // W_qkv^T split
__device__ __nv_bfloat16 g_woh[DD*DD],  g_wol[DD*DD];        // W_out^T split

__device__ __forceinline__ uint32_t smem_u32(const void* p) {
    uint32_t a;
    asm("{ .reg .u64 t; cvta.to.shared.u64 t, %1; cvt.u32.u64 %0, t; }"
        : "=r"(a) : "l"(p));
    return a;
}
#define SWZ(x) ((x) ^ (((x) >> 3) & 0x70))

#define LDSM4(r, addr) \
    asm volatile("ldmatrix.sync.aligned.m8n8.x4.shared.b16 {%0,%1,%2,%3}, [%4];" \
        : "=r"((r)[0]), "=r"((r)[1]), "=r"((r)[2]), "=r"((r)[3]) : "r"(addr))

#define MMA16816(d, a, b) \
    asm volatile("mma.sync.aligned.m16n8k16.row.col.f32.bf16.bf16.f32 " \
        "{%0,%1,%2,%3},{%4,%5,%6,%7},{%8,%9},{%0,%1,%2,%3};" \
        : "+f"((d)[0]), "+f"((d)[1]), "+f"((d)[2]), "+f"((d)[3]) \
        : "r"((a)[0]), "r"((a)[1]), "r"((a)[2]), "r"((a)[3]), \
          "r"((b)[0]), "r"((b)[1]))

#define GSMEM 132096   // 2 x 64KB buffers + 1KB align slack

// ---------------------------------------------------------------------------
// LayerNorm on strided rows -> split-bf16 A1 (hi/lo)
// ---------------------------------------------------------------------------
__global__ __launch_bounds__(256) void ln_kernel(const float* __restrict__ x,
                                                 const float* __restrict__ w,
                                                 const float* __restrict__ bias)
{
    int row = blockIdx.x;            // 0..4095 = b*TS + ts
    int b = row >> 10, ts = row & 1023;
    int tid = threadIdx.x;
    const float4* xr = (const float4*)(x + ((size_t)(b*TT + ts*4))*DD);
    float4 v = xr[tid];
    float s  = v.x + v.y + v.z + v.w;
    float sq = v.x*v.x + v.y*v.y + v.z*v.z + v.w*v.w;
    #pragma unroll
    for (int o = 16; o > 0; o >>= 1) {
        s  += __shfl_xor_sync(0xffffffffu, s,  o);
        sq += __shfl_xor_sync(0xffffffffu, sq, o);
    }
    __shared__ float rs[8], rq[8];
    int wid = tid >> 5, lane = tid & 31;
    if (lane == 0) { rs[wid] = s; rq[wid] = sq; }
    __syncthreads();
    if (tid == 0) {
        float S = 0.f, Q = 0.f;
        #pragma unroll
        for (int i = 0; i < 8; i++) { S += rs[i]; Q += rq[i]; }
        rs[0] = S; rq[0] = Q;
    }
    __syncthreads();
    float mean = rs[0] * (1.0f/DD);
    float var  = rq[0] * (1.0f/DD) - mean*mean;
    float rstd = rsqrtf(var + 1e-5f);
    float4 wv = ((const float4*)w)[tid];
    float4 bv = ((const float4*)bias)[tid];
    float vals[4];
    vals[0] = (v.x - mean)*rstd*wv.x + bv.x;
    vals[1] = (v.y - mean)*rstd*wv.y + bv.y;
    vals[2] = (v.z - mean)*rstd*wv.z + bv.z;
    vals[3] = (v.w - mean)*rstd*wv.w + bv.w;
    size_t base = (size_t)row*DD + tid*4;
    #pragma unroll
    for (int j = 0; j < 4; j += 2) {
        __nv_bfloat162 hh, ll;
        __nv_bfloat16 h0 = __float2bfloat16(vals[j]);
        __nv_bfloat16 h1 = __float2bfloat16(vals[j+1]);
        hh.x = h0; hh.y = h1;
        ll.x = __float2bfloat16(vals[j]   - __bfloat162float(h0));
        ll.y = __float2bfloat16(vals[j+1] - __bfloat162float(h1));
        *(__nv_bfloat162*)(g_a1h + base + j) = hh;
        *(__nv_bfloat162*)(g_a1l + base + j) = ll;
    }
}

// ---------------------------------------------------------------------------
// Weight transpose + split: W[K=1024][N] fp32 -> T[N][1024] bf16 hi/lo
// ---------------------------------------------------------------------------
__global__ __launch_bounds__(256) void wsplit(const float* __restrict__ W,
                                              __nv_bfloat16* __restrict__ Th,
                                              __nv_bfloat16* __restrict__ Tl,
                                              int N)
{
    __shared__ float t[32][33];
    int n0 = blockIdx.x*32, k0 = blockIdx.y*32;
    int tx = threadIdx.x & 31, ty = threadIdx.x >> 5;  // ty 0..7
    #pragma unroll
    for (int i = 0; i < 4; i++)
        t[ty + i*8][tx] = W[(size_t)(k0 + ty + i*8)*N + n0 + tx];
    __syncthreads();
    #pragma unroll
    for (int i = 0; i < 4; i++) {
        int n = n0 + ty + i*8, k = k0 + tx;
        float v = t[tx][ty + i*8];
        __nv_bfloat16 h = __float2bfloat16(v);
        __nv_bfloat16 l = __float2bfloat16(v - __bfloat162float(h));
        Th[(size_t)n*DD + k] = h;
        Tl[(size_t)n*DD + k] = l;
    }
}

// ---------------------------------------------------------------------------
// mma.sync split-bf16 GEMM: C[M,N] = A[M,1024] @ B^T + bias (B given [N][1024])
// Tile 128x128, K-chunk 64, cp.async double buffer, 8 warps (4m x 2n).
// 3 terms: Ah*Bh + Ah*Bl + Al*Bh into fp32 register accumulators.
// ---------------------------------------------------------------------------
__global__ __launch_bounds__(256, 1)
void gemm_mma(const __nv_bfloat16* __restrict__ Ah, const __nv_bfloat16* __restrict__ Al,
              const __nv_bfloat16* __restrict__ Bh, const __nv_bfloat16* __restrict__ Bl,
              const float* __restrict__ bias, float* __restrict__ C, int ldc)
{
    extern __shared__ char dsm[];
    uint32_t sb = (smem_u32(dsm) + 1023) & ~1023u;
    int tid = threadIdx.x, lane = tid & 31, wid = tid >> 5;
    int bn = blockIdx.x*128, bm = blockIdx.y*128;
    int m0 = (wid & 3)*32, n0 = (wid >> 2)*64;

    // gmem->smem copy mapping: thread covers row=tid/2, 64B half-row
    int row = tid >> 1, half = tid & 1;
    const uint4* gsrc[4] = {
        (const uint4*)(Ah + (size_t)(bm+row)*DD) + half*4,
        (const uint4*)(Al + (size_t)(bm+row)*DD) + half*4,
        (const uint4*)(Bh + (size_t)(bn+row)*DD) + half*4,
        (const uint4*)(Bl + (size_t)(bn+row)*DD) + half*4 };
    uint32_t so = (uint32_t)(row*128 + half*64);

    float acc[2][8][4];
    #pragma unroll
    for (int i = 0; i < 2; i++)
        #pragma unroll
        for (int j = 0; j < 8; j++)
            #pragma unroll
            for (int k = 0; k < 4; k++) acc[i][j][k] = 0.f;

    auto copy_chunk = [&](int c, int buf) {
        uint32_t bbase = sb + buf*65536;
        #pragma unroll
        for (int a = 0; a < 4; a++) {
            const uint4* src = gsrc[a] + c*8;
            uint32_t dst = bbase + a*16384;
            #pragma unroll
            for (int i = 0; i < 4; i++) {
                uint32_t d = dst + SWZ(so + i*16);
                asm volatile("cp.async.cg.shared.global [%0], [%1], 16;"
                             :: "r"(d), "l"(src + i) : "memory");
            }
        }
        asm volatile("cp.async.commit_group;" ::: "memory");
    };

    copy_chunk(0, 0);

    for (int c = 0; c < 16; c++) {
        asm volatile("cp.async.wait_group 0;" ::: "memory");
        __syncthreads();
        if (c < 15) copy_chunk(c + 1, (c + 1) & 1);

        uint32_t bbase = sb + (c & 1)*65536;
        #pragma unroll
        for (int ks = 0; ks < 4; ks++) {
            uint32_t a_h[2][4], a_l[2][4];
            #pragma unroll
            for (int mi = 0; mi < 2; mi++) {
                int r  = m0 + mi*16 + (lane & 15);
                int kb = ks*16 + (lane >> 4)*8;
                uint32_t ad = SWZ((uint32_t)(r*128 + kb*2));
                LDSM4(a_h[mi], bbase + ad);
                LDSM4(a_l[mi], bbase + 16384 + ad);
            }
            #pragma unroll
            for (int nj = 0; nj < 4; nj++) {
                int rn = n0 + nj*16 + (lane & 7) + ((lane >> 4) & 1)*8;
                int kb = ks*16 + ((lane >> 3) & 1)*8;
                uint32_t ad = SWZ((uint32_t)(rn*128 + kb*2));
                uint32_t b_h[4], b_l[4];
                LDSM4(b_h, bbase + 32768 + ad);
                LDSM4(b_l, bbase + 49152 + ad);
                #pragma unroll
                for (int mi = 0; mi < 2; mi++) {
                    #pragma unroll
                    for (int t = 0; t < 2; t++) {
                        float* d = acc[mi][nj*2 + t];
                        MMA16816(d, a_h[mi], b_h + t*2);
                        MMA16816(d, a_h[mi], b_l + t*2);
                        MMA16816(d, a_l[mi], b_h + t*2);
                    }
                }
            }
        }
    }

    // Epilogue: registers -> gmem with bias (c0,c1 row lane/4; c2,c3 row+8)
    #pragma unroll
    for (int mi = 0; mi < 2; mi++) {
        int r0 = bm + m0 + mi*16 + (lane >> 2);
        #pragma unroll
        for (int nt = 0; nt < 8; nt++) {
            int col = bn + n0 + nt*8 + (lane & 3)*2;
            float2 bv = *(const float2*)(bias + col);
            float2 v0, v1;
            v0.x = acc[mi][nt][0] + bv.x; v0.y = acc[mi][nt][1] + bv.y;
            v1.x = acc[mi][nt][2] + bv.x; v1.y = acc[mi][nt][3] + bv.y;
            *(float2*)(C + (size_t)r0*ldc + col)     = v0;
            *(float2*)(C + (size_t)(r0+8)*ldc + col) = v1;
        }
    }
}

// ---------------------------------------------------------------------------
// RoPE in-place on q,k parts of g_qkv.
// ---------------------------------------------------------------------------
__global__ __launch_bounds__(256) void rope_kernel()
{
    int idx = blockIdx.x * 256 + threadIdx.x;   // 2^21 total
    int i  = idx & 31;
    int h  = (idx >> 5) & 15;
    int ts = (idx >> 9) & 1023;
    int b  = idx >> 19;
    float freq = expf(-(float)(2*i) * (9.210340371976184f / 64.0f));
    float ang = (float)ts * freq;
    float sn, cs;
    sincosf(ang, &sn, &cs);
    int base = (b*TS + ts)*3*DD + h*HD;
    float q0 = g_qkv[base+i], q1 = g_qkv[base+i+32];
    g_qkv[base+i]    = q0*cs - q1*sn;
    g_qkv[base+i+32] = q1*cs + q0*sn;
    base += DD;
    float k0 = g_qkv[base+i], k1 = g_qkv[base+i+32];
    g_qkv[base+i]    = k0*cs - k1*sn;
    g_qkv[base+i+32] = k1*cs + k0*sn;
}

// ---------------------------------------------------------------------------
// Causal flash attention (fp32).  Writes split-bf16 output for GEMM2.
// ---------------------------------------------------------------------------
__global__ __launch_bounds__(128) void attn_kernel()
{
    __shared__ float Qts[64][65];
    __shared__ float Kts[64][33];
    __shared__ float Vs[32][64];
    __shared__ float Ss[64][33];
    __shared__ float row_m[64], row_l[64], row_a[64];

    int tid  = threadIdx.x;
    int qblk = blockIdx.x;
    int bh   = blockIdx.y;
    int b = bh >> 4, h = bh & 15;

    const float* qbase = g_qkv + (size_t)(b*TS + qblk*64)*3*DD + h*HD;
    int ld_m = tid >> 4;
    int ld_c = (tid & 15) * 4;
    #pragma unroll
    for (int r = 0; r < 8; r++) {
        int m = ld_m + 8*r;
        float4 v = *(const float4*)(qbase + (size_t)m*3*DD + ld_c);
        Qts[ld_c+0][m] = v.x*0.125f; Qts[ld_c+1][m] = v.y*0.125f;
        Qts[ld_c+2][m] = v.z*0.125f; Qts[ld_c+3][m] = v.w*0.125f;
    }
    if (tid < 64) { row_m[tid] = -1e30f; row_l[tid] = 0.f; }

    float o[4][8];
    #pragma unroll
    for (int i = 0; i < 4; i++)
        #pragma unroll
        for (int j = 0; j < 8; j++) o[i][j] = 0.f;

    int sy = tid >> 2;
    int sx = (tid & 3) * 8;
    int py = tid >> 3;
    int px = (tid & 7) * 8;

    int nkt = 2*qblk + 2;
    for (int kt = 0; kt < nkt; kt++) {
        const float* kb = g_qkv + (size_t)(b*TS + kt*32)*3*DD + DD + h*HD
                        + (size_t)(tid >> 4)*3*DD + ld_c;
        float4 kv4[4], vv4[4];
        #pragma unroll
        for (int r = 0; r < 4; r++) {
            kv4[r] = *(const float4*)(kb + (size_t)(8*r)*3*DD);
            vv4[r] = *(const float4*)(kb + (size_t)(8*r)*3*DD + DD);
        }
        __syncthreads();
        #pragma unroll
        for (int r = 0; r < 4; r++) {
            int n = (tid >> 4) + 8*r;
            Kts[ld_c+0][n] = kv4[r].x; Kts[ld_c+1][n] = kv4[r].y;
            Kts[ld_c+2][n] = kv4[r].z; Kts[ld_c+3][n] = kv4[r].w;
            *(float4*)&Vs[n][ld_c] = vv4[r];
        }
        __syncthreads();

        float s[2][8];
        #pragma unroll
        for (int j = 0; j < 8; j++) { s[0][j] = 0.f; s[1][j] = 0.f; }
        #pragma unroll 8
        for (int d = 0; d < 64; d++) {
            float q0 = Qts[d][2*sy], q1 = Qts[d][2*sy+1];
            #pragma unroll
            for (int j = 0; j < 8; j++) {
                float kvv = Kts[d][sx+j];
                s[0][j] = fmaf(q0, kvv, s[0][j]);
                s[1][j] = fmaf(q1, kvv, s[1][j]);
            }
        }

        #pragma unroll
        for (int i = 0; i < 2; i++) {
            int rr = 2*sy + i;
            int qrow = qblk*64 + rr;
            float mx = -1e30f;
            #pragma unroll
            for (int j = 0; j < 8; j++) {
                int kc = kt*32 + sx + j;
                if (kc > qrow) s[i][j] = -1e30f;
                mx = fmaxf(mx, s[i][j]);
            }
            mx = fmaxf(mx, __shfl_xor_sync(0xffffffffu, mx, 1));
            mx = fmaxf(mx, __shfl_xor_sync(0xffffffffu, mx, 2));
            float mo = row_m[rr];
            float mn = fmaxf(mo, mx);
            float al = __expf(mo - mn);
            float sum = 0.f;
            #pragma unroll
            for (int j = 0; j < 8; j++) {
                float p = __expf(s[i][j] - mn);
                s[i][j] = p;
                sum += p;
            }
            sum += __shfl_xor_sync(0xffffffffu, sum, 1);
            sum += __shfl_xor_sync(0xffffffffu, sum, 2);
            if ((tid & 3) == 0) {
                row_m[rr] = mn;
                row_a[rr] = al;
                row_l[rr] = row_l[rr]*al + sum;
            }
            #pragma unroll
            for (int j = 0; j < 8; j++) Ss[rr][sx+j] = s[i][j];
        }
        __syncthreads();

        #pragma unroll
        for (int i = 0; i < 4; i++) {
            float al = row_a[py*4 + i];
            #pragma unroll
            for (int j = 0; j < 8; j++) o[i][j] *= al;
        }
        #pragma unroll 8
        for (int n = 0; n < 32; n++) {
            float pv[4];
            #pragma unroll
            for (int i = 0; i < 4; i++) pv[i] = Ss[py*4+i][n];
            #pragma unroll
            for (int j = 0; j < 8; j++) {
                float vvv = Vs[n][px+j];
                #pragma unroll
                for (int i = 0; i < 4; i++)
                    o[i][j] = fmaf(pv[i], vvv, o[i][j]);
            }
        }
    }
    __syncthreads();

    // Finalize -> split bf16 for GEMM2
    #pragma unroll
    for (int i = 0; i < 4; i++) {
        int m = py*4 + i;
        float inv = 1.0f / row_l[m];
        size_t ob = (size_t)(b*TS + qblk*64 + m)*DD + h*HD + px;
        #pragma unroll
        for (int j = 0; j < 8; j += 2) {
            float v0 = o[i][j]*inv, v1 = o[i][j+1]*inv;
            __nv_bfloat162 hh, ll;
            hh.x = __float2bfloat16(v0);
            hh.y = __float2bfloat16(v1);
            ll.x = __float2bfloat16(v0 - __bfloat162float(hh.x));
            ll.y = __float2bfloat16(v1 - __bfloat162float(hh.y));
            *(__nv_bfloat162*)(g_a2h + ob + j) = hh;
            *(__nv_bfloat162*)(g_a2l + ob + j) = ll;
        }
    }
}

// ---------------------------------------------------------------------------
// Linear upsample Ts->T (scale 0.25) + residual add.
// ---------------------------------------------------------------------------
__global__ __launch_bounds__(256) void upsample_kernel(const float* __restrict__ x,
                                                       float* __restrict__ outp)
{
    int gid = blockIdx.x * 256 + threadIdx.x;
    int d4 = gid & 255;
    int t  = (gid >> 8) & (TT - 1);
    int b  = gid >> 20;
    float src = ((float)t + 0.5f) * ((float)TS / (float)TT) - 0.5f;
    src = fminf(fmaxf(src, 0.0f), (float)(TS - 1));
    float fi0 = floorf(src);
    int i0 = (int)fi0;
    int i1 = min(i0 + 1, TS - 1);
    float w  = src - fi0;
    float w0 = 1.0f - w;
    const float4* pr = (const float4*)g_proj;
    float4 p0 = pr[(b*TS + i0)*256 + d4];
    float4 p1 = pr[(b*TS + i1)*256 + d4];
    float4 xv = ((const float4*)x)[gid];
    float4 ov;
    ov.x = xv.x + p0.x*w0 + p1.x*w;
    ov.y = xv.y + p0.y*w0 + p1.y*w;
    ov.z = xv.z + p0.z*w0 + p1.z*w;
    ov.w = xv.w + p0.w*w0 + p1.w*w;
    ((float4*)outp)[gid] = ov;
}

// ---------------------------------------------------------------------------
extern "C" void kernel_launch(void* const* d_in, const int* in_sizes, int n_in,
                              void* d_out, int out_size)
{
    const float* x      = (const float*)d_in[0];
    const float* norm_w = (const float*)d_in[1];
    const float* norm_b = (const float*)d_in[2];
    const float* W_qkv  = (const float*)d_in[3];
    const float* b_qkv  = (const float*)d_in[4];
    const float* W_out  = (const float*)d_in[5];
    const float* b_out  = (const float*)d_in[6];
    float* out = (float*)d_out;

    // Idempotent; called every invocation (no static guards allowed).
    cudaFuncSetAttribute(gemm_mma, cudaFuncAttributeMaxDynamicSharedMemorySize, GSMEM);

    float *qkv_p, *proj_p;
    __nv_bfloat16 *a1h, *a1l, *a2h, *a2l, *wqh, *wql, *woh, *wol;
    cudaGetSymbolAddress((void**)&qkv_p,  g_qkv);
    cudaGetSymbolAddress((void**)&proj_p, g_proj);
    cudaGetSymbolAddress((void**)&a1h, g_a1h);
    cudaGetSymbolAddress((void**)&a1l, g_a1l);
    cudaGetSymbolAddress((void**)&a2h, g_a2h);
    cudaGetSymbolAddress((void**)&a2l, g_a2l);
    cudaGetSymbolAddress((void**)&wqh, g_wqh);
    cudaGetSymbolAddress((void**)&wql, g_wql);
    cudaGetSymbolAddress((void**)&woh, g_woh);
    cudaGetSymbolAddress((void**)&wol, g_wol);

    ln_kernel<<<MROWS, 256>>>(x, norm_w, norm_b);
    wsplit<<<dim3(3*DD/32, DD/32), 256>>>(W_qkv, wqh, wql, 3*DD);
    wsplit<<<dim3(DD/32, DD/32), 256>>>(W_out, woh, wol, DD);

    gemm_mma<<<dim3(3*DD/128, MROWS/128), 256, GSMEM>>>(a1h, a1l, wqh, wql,
                                                        b_qkv, qkv_p, 3*DD);
    rope_kernel<<<(BB*TS*HH*32)/256, 256>>>();
    attn_kernel<<<dim3(TS/64, BB*HH), 128>>>();
    gemm_mma<<<dim3(DD/128, MROWS/128), 256, GSMEM>>>(a2h, a2l, woh, wol,
                                                      b_out, proj_p, DD);
    upsample_kernel<<<(BB*TT*DD/4)/256, 256>>>(x, out);
}

// round 11
// speedup vs baseline: 2.3699x; 1.5828x over previous
#include <cuda_runtime.h>
#include <cuda_bf16.h>
#include <math.h>
#include <stdint.h>

// Problem constants
#define BB 4
#define TT 4096
#define DD 1024
#define HH 16
#define HD 64
#define TS 1024
#define MROWS (BB*TS)
#define BH (BB*HH)

// Scratch (allocation-free: __device__ globals)
__device__ float g_qkv[MROWS*3*DD];                          // 48 MB qkv fp32
__device__ float g_proj[MROWS*DD];                           // 16 MB out projection
__device__ __nv_bfloat16 g_a1h[MROWS*DD], g_a1l[MROWS*DD];   // LN rows, split bf16
__device__ __nv_bfloat16 g_a2h[MROWS*DD], g_a2l[MROWS*DD];   // attn out, split bf16
__device__ __nv_bfloat16 g_wqh[3*DD*DD], g_wql[3*DD*DD];     // W_qkv^T split
__device__ __nv_bfloat16 g_woh[DD*DD],  g_wol[DD*DD];        // W_out^T split
// RoPE'd split-bf16 attention operands, [B,H,Ts,64]
__device__ __nv_bfloat16 g_qh[BH*TS*HD], g_ql[BH*TS*HD];
__device__ __nv_bfloat16 g_kh[BH*TS*HD], g_kl[BH*TS*HD];
__device__ __nv_bfloat16 g_vh[BH*TS*HD], g_vl[BH*TS*HD];

__device__ __forceinline__ uint32_t smem_u32(const void* p) {
    uint32_t a;
    asm("{ .reg .u64 t; cvta.to.shared.u64 t, %1; cvt.u32.u64 %0, t; }"
        : "=r"(a) : "l"(p));
    return a;
}
#define SWZ(x) ((x) ^ (((x) >> 3) & 0x70))

#define LDSM4(r, addr) \
    asm volatile("ldmatrix.sync.aligned.m8n8.x4.shared.b16 {%0,%1,%2,%3}, [%4];" \
        : "=r"((r)[0]), "=r"((r)[1]), "=r"((r)[2]), "=r"((r)[3]) : "r"(addr))

#define LDSM4T(r, addr) \
    asm volatile("ldmatrix.sync.aligned.m8n8.x4.trans.shared.b16 {%0,%1,%2,%3}, [%4];" \
        : "=r"((r)[0]), "=r"((r)[1]), "=r"((r)[2]), "=r"((r)[3]) : "r"(addr))

#define MMA16816(d, a, b) \
    asm volatile("mma.sync.aligned.m16n8k16.row.col.f32.bf16.bf16.f32 " \
        "{%0,%1,%2,%3},{%4,%5,%6,%7},{%8,%9},{%0,%1,%2,%3};" \
        : "+f"((d)[0]), "+f"((d)[1]), "+f"((d)[2]), "+f"((d)[3]) \
        : "r"((a)[0]), "r"((a)[1]), "r"((a)[2]), "r"((a)[3]), \
          "r"((b)[0]), "r"((b)[1]))

#define CPA16(dst, src) \
    asm volatile("cp.async.cg.shared.global [%0], [%1], 16;" :: "r"(dst), "l"(src) : "memory")
#define CPA_COMMIT() asm volatile("cp.async.commit_group;" ::: "memory")
#define CPA_WAIT0()  asm volatile("cp.async.wait_group 0;" ::: "memory")

#define GSMEM 132096     // gemm: 2 x 64KB + align slack
#define ATT_SMEM 82944   // attn: 2 x 32KB (K/V hi/lo) + 16KB Q + slack

__device__ __forceinline__ void pack_split(float a, float b, uint32_t& hi, uint32_t& lo) {
    __nv_bfloat162 h = __floats2bfloat162_rn(a, b);
    float ra = a - __bfloat162float(h.x);
    float rb = b - __bfloat162float(h.y);
    __nv_bfloat162 l2 = __floats2bfloat162_rn(ra, rb);
    hi = *(uint32_t*)&h;
    lo = *(uint32_t*)&l2;
}

// ---------------------------------------------------------------------------
// LayerNorm on strided rows -> split-bf16 A1 (hi/lo)
// ---------------------------------------------------------------------------
__global__ __launch_bounds__(256) void ln_kernel(const float* __restrict__ x,
                                                 const float* __restrict__ w,
                                                 const float* __restrict__ bias)
{
    int row = blockIdx.x;
    int b = row >> 10, ts = row & 1023;
    int tid = threadIdx.x;
    const float4* xr = (const float4*)(x + ((size_t)(b*TT + ts*4))*DD);
    float4 v = xr[tid];
    float s  = v.x + v.y + v.z + v.w;
    float sq = v.x*v.x + v.y*v.y + v.z*v.z + v.w*v.w;
    #pragma unroll
    for (int o = 16; o > 0; o >>= 1) {
        s  += __shfl_xor_sync(0xffffffffu, s,  o);
        sq += __shfl_xor_sync(0xffffffffu, sq, o);
    }
    __shared__ float rs[8], rq[8];
    int wid = tid >> 5, lane = tid & 31;
    if (lane == 0) { rs[wid] = s; rq[wid] = sq; }
    __syncthreads();
    if (tid == 0) {
        float S = 0.f, Q = 0.f;
        #pragma unroll
        for (int i = 0; i < 8; i++) { S += rs[i]; Q += rq[i]; }
        rs[0] = S; rq[0] = Q;
    }
    __syncthreads();
    float mean = rs[0] * (1.0f/DD);
    float var  = rq[0] * (1.0f/DD) - mean*mean;
    float rstd = rsqrtf(var + 1e-5f);
    float4 wv = ((const float4*)w)[tid];
    float4 bv = ((const float4*)bias)[tid];
    float vals[4];
    vals[0] = (v.x - mean)*rstd*wv.x + bv.x;
    vals[1] = (v.y - mean)*rstd*wv.y + bv.y;
    vals[2] = (v.z - mean)*rstd*wv.z + bv.z;
    vals[3] = (v.w - mean)*rstd*wv.w + bv.w;
    size_t base = (size_t)row*DD + tid*4;
    #pragma unroll
    for (int j = 0; j < 4; j += 2) {
        uint32_t H, L;
        pack_split(vals[j], vals[j+1], H, L);
        *(uint32_t*)(g_a1h + base + j) = H;
        *(uint32_t*)(g_a1l + base + j) = L;
    }
}

// ---------------------------------------------------------------------------
// Weight transpose + split: W[K=1024][N] fp32 -> T[N][1024] bf16 hi/lo
// ---------------------------------------------------------------------------
__global__ __launch_bounds__(256) void wsplit(const float* __restrict__ W,
                                              __nv_bfloat16* __restrict__ Th,
                                              __nv_bfloat16* __restrict__ Tl,
                                              int N)
{
    __shared__ float t[32][33];
    int n0 = blockIdx.x*32, k0 = blockIdx.y*32;
    int tx = threadIdx.x & 31, ty = threadIdx.x >> 5;
    #pragma unroll
    for (int i = 0; i < 4; i++)
        t[ty + i*8][tx] = W[(size_t)(k0 + ty + i*8)*N + n0 + tx];
    __syncthreads();
    #pragma unroll
    for (int i = 0; i < 4; i++) {
        int n = n0 + ty + i*8, k = k0 + tx;
        float v = t[tx][ty + i*8];
        __nv_bfloat16 h = __float2bfloat16(v);
        __nv_bfloat16 l = __float2bfloat16(v - __bfloat162float(h));
        Th[(size_t)n*DD + k] = h;
        Tl[(size_t)n*DD + k] = l;
    }
}

// ---------------------------------------------------------------------------
// mma.sync split-bf16 GEMM (validated round 10): C = A @ B^T + bias
// ---------------------------------------------------------------------------
__global__ __launch_bounds__(256, 1)
void gemm_mma(const __nv_bfloat16* __restrict__ Ah, const __nv_bfloat16* __restrict__ Al,
              const __nv_bfloat16* __restrict__ Bh, const __nv_bfloat16* __restrict__ Bl,
              const float* __restrict__ bias, float* __restrict__ C, int ldc)
{
    extern __shared__ char dsm[];
    uint32_t sb = (smem_u32(dsm) + 1023) & ~1023u;
    int tid = threadIdx.x, lane = tid & 31, wid = tid >> 5;
    int bn = blockIdx.x*128, bm = blockIdx.y*128;
    int m0 = (wid & 3)*32, n0 = (wid >> 2)*64;

    int row = tid >> 1, half = tid & 1;
    const uint4* gsrc[4] = {
        (const uint4*)(Ah + (size_t)(bm+row)*DD) + half*4,
        (const uint4*)(Al + (size_t)(bm+row)*DD) + half*4,
        (const uint4*)(Bh + (size_t)(bn+row)*DD) + half*4,
        (const uint4*)(Bl + (size_t)(bn+row)*DD) + half*4 };
    uint32_t so = (uint32_t)(row*128 + half*64);

    float acc[2][8][4];
    #pragma unroll
    for (int i = 0; i < 2; i++)
        #pragma unroll
        for (int j = 0; j < 8; j++)
            #pragma unroll
            for (int k = 0; k < 4; k++) acc[i][j][k] = 0.f;

    auto copy_chunk = [&](int c, int buf) {
        uint32_t bbase = sb + buf*65536;
        #pragma unroll
        for (int a = 0; a < 4; a++) {
            const uint4* src = gsrc[a] + c*8;
            uint32_t dst = bbase + a*16384;
            #pragma unroll
            for (int i = 0; i < 4; i++)
                CPA16(dst + SWZ(so + i*16), src + i);
        }
        CPA_COMMIT();
    };

    copy_chunk(0, 0);

    for (int c = 0; c < 16; c++) {
        CPA_WAIT0();
        __syncthreads();
        if (c < 15) copy_chunk(c + 1, (c + 1) & 1);

        uint32_t bbase = sb + (c & 1)*65536;
        #pragma unroll
        for (int ks = 0; ks < 4; ks++) {
            uint32_t a_h[2][4], a_l[2][4];
            #pragma unroll
            for (int mi = 0; mi < 2; mi++) {
                int r  = m0 + mi*16 + (lane & 15);
                int kb = ks*16 + (lane >> 4)*8;
                uint32_t ad = SWZ((uint32_t)(r*128 + kb*2));
                LDSM4(a_h[mi], bbase + ad);
                LDSM4(a_l[mi], bbase + 16384 + ad);
            }
            #pragma unroll
            for (int nj = 0; nj < 4; nj++) {
                int rn = n0 + nj*16 + (lane & 7) + ((lane >> 4) & 1)*8;
                int kb = ks*16 + ((lane >> 3) & 1)*8;
                uint32_t ad = SWZ((uint32_t)(rn*128 + kb*2));
                uint32_t b_h[4], b_l[4];
                LDSM4(b_h, bbase + 32768 + ad);
                LDSM4(b_l, bbase + 49152 + ad);
                #pragma unroll
                for (int mi = 0; mi < 2; mi++) {
                    #pragma unroll
                    for (int t = 0; t < 2; t++) {
                        float* d = acc[mi][nj*2 + t];
                        MMA16816(d, a_h[mi], b_h + t*2);
                        MMA16816(d, a_h[mi], b_l + t*2);
                        MMA16816(d, a_l[mi], b_h + t*2);
                    }
                }
            }
        }
    }

    #pragma unroll
    for (int mi = 0; mi < 2; mi++) {
        int r0 = bm + m0 + mi*16 + (lane >> 2);
        #pragma unroll
        for (int nt = 0; nt < 8; nt++) {
            int col = bn + n0 + nt*8 + (lane & 3)*2;
            float2 bv = *(const float2*)(bias + col);
            float2 v0, v1;
            v0.x = acc[mi][nt][0] + bv.x; v0.y = acc[mi][nt][1] + bv.y;
            v1.x = acc[mi][nt][2] + bv.x; v1.y = acc[mi][nt][3] + bv.y;
            *(float2*)(C + (size_t)r0*ldc + col)     = v0;
            *(float2*)(C + (size_t)(r0+8)*ldc + col) = v1;
        }
    }
}

// ---------------------------------------------------------------------------
// RoPE + split-bf16 conversion: g_qkv fp32 -> Q(,*0.125)/K/V split [B,H,Ts,64]
// ---------------------------------------------------------------------------
__global__ __launch_bounds__(256) void rope_split()
{
    int idx = blockIdx.x * 256 + threadIdx.x;   // BH*TS*32
    int i  = idx & 31;
    int h  = (idx >> 5) & 15;
    int ts = (idx >> 9) & 1023;
    int b  = idx >> 19;
    float freq = expf(-(float)(2*i) * (9.210340371976184f / 64.0f));
    float ang = (float)ts * freq;
    float sn, cs;
    sincosf(ang, &sn, &cs);
    size_t src = ((size_t)(b*TS + ts))*3*DD + h*HD;
    float q0 = g_qkv[src+i],      q1 = g_qkv[src+i+32];
    float k0 = g_qkv[src+DD+i],   k1 = g_qkv[src+DD+i+32];
    float v0 = g_qkv[src+2*DD+i], v1 = g_qkv[src+2*DD+i+32];
    float qr0 = (q0*cs - q1*sn) * 0.125f;
    float qr1 = (q1*cs + q0*sn) * 0.125f;
    float kr0 = k0*cs - k1*sn;
    float kr1 = k1*cs + k0*sn;
    size_t dst = ((size_t)((b*HH + h)*TS + ts))*HD;
    __nv_bfloat16 t;
    t = __float2bfloat16(qr0); g_qh[dst+i]    = t; g_ql[dst+i]    = __float2bfloat16(qr0 - __bfloat162float(t));
    t = __float2bfloat16(qr1); g_qh[dst+i+32] = t; g_ql[dst+i+32] = __float2bfloat16(qr1 - __bfloat162float(t));
    t = __float2bfloat16(kr0); g_kh[dst+i]    = t; g_kl[dst+i]    = __float2bfloat16(kr0 - __bfloat162float(t));
    t = __float2bfloat16(kr1); g_kh[dst+i+32] = t; g_kl[dst+i+32] = __float2bfloat16(kr1 - __bfloat162float(t));
    t = __float2bfloat16(v0);  g_vh[dst+i]    = t; g_vl[dst+i]    = __float2bfloat16(v0 - __bfloat162float(t));
    t = __float2bfloat16(v1);  g_vh[dst+i+32] = t; g_vl[dst+i+32] = __float2bfloat16(v1 - __bfloat162float(t));
}

// ---------------------------------------------------------------------------
// Causal flash attention on mma.sync, split-bf16 QK^T and PV.
// CTA = (64 q-rows, head). 4 warps x 16 rows. K/V tiles of 64 keys,
// cp.async double-buffered. P kept in registers (C-frag -> A-frag).
// Writes split-bf16 output for GEMM2.
// ---------------------------------------------------------------------------
__global__ __launch_bounds__(128, 1) void attn_mma()
{
    extern __shared__ char dsm[];
    uint32_t sb = (smem_u32(dsm) + 1023) & ~1023u;
    int tid = threadIdx.x, lane = tid & 31, wid = tid >> 5;
    int qblk = 15 - blockIdx.x;      // big q-blocks first (load balance)
    int bh   = blockIdx.y;
    size_t head = (size_t)bh*TS*HD;

    const uint32_t QH = sb + 65536, QL = QH + 8192;
    int crow = tid >> 1, chalf = tid & 1;
    uint32_t cso = (uint32_t)(crow*128 + chalf*64);

    // Prefetch K/V tile 0 (hi/lo) via cp.async
    auto load_tile = [&](int kt, int s) {
        uint32_t bb = sb + s*32768;
        size_t src = head + (size_t)(kt*64 + crow)*HD + chalf*32;
        const uint4* pk_h = (const uint4*)(g_kh + src);
        const uint4* pk_l = (const uint4*)(g_kl + src);
        const uint4* pv_h = (const uint4*)(g_vh + src);
        const uint4* pv_l = (const uint4*)(g_vl + src);
        #pragma unroll
        for (int i = 0; i < 4; i++) {
            uint32_t sw = SWZ(cso + i*16);
            CPA16(bb + sw,         pk_h + i);
            CPA16(bb +  8192 + sw, pk_l + i);
            CPA16(bb + 16384 + sw, pv_h + i);
            CPA16(bb + 24576 + sw, pv_l + i);
        }
        CPA_COMMIT();
    };
    load_tile(0, 0);

    // Q tile (64x64 hi/lo) -> smem (plain ld/st, overlaps with cp.async)
    {
        size_t qsrc = head + (size_t)(qblk*64 + crow)*HD + chalf*32;
        #pragma unroll
        for (int i = 0; i < 4; i++) {
            uint32_t sw = SWZ(cso + i*16);
            *(uint4*)(dsm + (QH - smem_u32(dsm)) + sw) = *(const uint4*)(g_qh + qsrc + i*8);
            *(uint4*)(dsm + (QL - smem_u32(dsm)) + sw) = *(const uint4*)(g_ql + qsrc + i*8);
        }
    }

    float o[8][4];
    #pragma unroll
    for (int j = 0; j < 8; j++)
        #pragma unroll
        for (int k = 0; k < 4; k++) o[j][k] = 0.f;
    float m0 = -1e30f, m1 = -1e30f, l0 = 0.f, l1 = 0.f;
    int r = lane >> 2, c = lane & 3;

    for (int kt = 0; kt <= qblk; kt++) {
        CPA_WAIT0();
        __syncthreads();
        if (kt < qblk) load_tile(kt + 1, (kt + 1) & 1);
        uint32_t bb = sb + (kt & 1)*32768;

        // --- scores S[16 x 64] per warp, 3-term split ---
        float s[8][4];
        #pragma unroll
        for (int j = 0; j < 8; j++)
            #pragma unroll
            for (int k = 0; k < 4; k++) s[j][k] = 0.f;

        #pragma unroll
        for (int ks = 0; ks < 4; ks++) {
            uint32_t aq = SWZ((uint32_t)((wid*16 + (lane & 15))*128 + (ks*16 + 8*(lane >> 4))*2));
            uint32_t a_h[4], a_l[4];
            LDSM4(a_h, QH + aq);
            LDSM4(a_l, QL + aq);
            #pragma unroll
            for (int nj = 0; nj < 4; nj++) {
                uint32_t bad = SWZ((uint32_t)((nj*16 + (lane & 7) + ((lane >> 4) & 1)*8)*128
                                              + (ks*16 + ((lane >> 3) & 1)*8)*2));
                uint32_t b_h[4], b_l[4];
                LDSM4(b_h, bb + bad);
                LDSM4(b_l, bb + 8192 + bad);
                #pragma unroll
                for (int t = 0; t < 2; t++) {
                    float* d = s[nj*2 + t];
                    MMA16816(d, a_h, b_h + t*2);
                    MMA16816(d, a_h, b_l + t*2);
                    MMA16816(d, a_l, b_h + t*2);
                }
            }
        }

        // --- causal mask (diagonal tile only) ---
        if (kt == qblk) {
            int row0 = wid*16 + r, row1 = row0 + 8;
            #pragma unroll
            for (int j = 0; j < 8; j++) {
                int col = j*8 + 2*c;
                if (col     > row0) s[j][0] = -1e30f;
                if (col + 1 > row0) s[j][1] = -1e30f;
                if (col     > row1) s[j][2] = -1e30f;
                if (col + 1 > row1) s[j][3] = -1e30f;
            }
        }

        // --- online softmax on fragments ---
        float mx0 = -1e30f, mx1 = -1e30f;
        #pragma unroll
        for (int j = 0; j < 8; j++) {
            mx0 = fmaxf(mx0, fmaxf(s[j][0], s[j][1]));
            mx1 = fmaxf(mx1, fmaxf(s[j][2], s[j][3]));
        }
        mx0 = fmaxf(mx0, __shfl_xor_sync(0xffffffffu, mx0, 1));
        mx0 = fmaxf(mx0, __shfl_xor_sync(0xffffffffu, mx0, 2));
        mx1 = fmaxf(mx1, __shfl_xor_sync(0xffffffffu, mx1, 1));
        mx1 = fmaxf(mx1, __shfl_xor_sync(0xffffffffu, mx1, 2));
        float mn0 = fmaxf(m0, mx0), mn1 = fmaxf(m1, mx1);
        float al0 = __expf(m0 - mn0), al1 = __expf(m1 - mn1);
        m0 = mn0; m1 = mn1;
        float sum0 = 0.f, sum1 = 0.f;
        #pragma unroll
        for (int j = 0; j < 8; j++) {
            s[j][0] = __expf(s[j][0] - mn0); sum0 += s[j][0];
            s[j][1] = __expf(s[j][1] - mn0); sum0 += s[j][1];
            s[j][2] = __expf(s[j][2] - mn1); sum1 += s[j][2];
            s[j][3] = __expf(s[j][3] - mn1); sum1 += s[j][3];
        }
        sum0 += __shfl_xor_sync(0xffffffffu, sum0, 1);
        sum0 += __shfl_xor_sync(0xffffffffu, sum0, 2);
        sum1 += __shfl_xor_sync(0xffffffffu, sum1, 1);
        sum1 += __shfl_xor_sync(0xffffffffu, sum1, 2);
        l0 = l0*al0 + sum0;
        l1 = l1*al1 + sum1;
        #pragma unroll
        for (int j = 0; j < 8; j++) {
            o[j][0] *= al0; o[j][1] *= al0;
            o[j][2] *= al1; o[j][3] *= al1;
        }

        // --- P (C-frags) -> A-frags, split bf16 ---
        uint32_t ph[4][4], pl[4][4];
        #pragma unroll
        for (int cc = 0; cc < 4; cc++) {
            int j = 2*cc;
            pack_split(s[j][0],   s[j][1],   ph[cc][0], pl[cc][0]);
            pack_split(s[j][2],   s[j][3],   ph[cc][1], pl[cc][1]);
            pack_split(s[j+1][0], s[j+1][1], ph[cc][2], pl[cc][2]);
            pack_split(s[j+1][2], s[j+1][3], ph[cc][3], pl[cc][3]);
        }

        // --- PV: o += P @ V, V B-frags via ldmatrix.trans ---
        #pragma unroll
        for (int cc = 0; cc < 4; cc++) {
            #pragma unroll
            for (int db = 0; db < 4; db++) {
                uint32_t vad = SWZ((uint32_t)((cc*16 + (lane & 15))*128
                                              + (db*16 + 8*(lane >> 4))*2));
                uint32_t v_h[4], v_l[4];
                LDSM4T(v_h, bb + 16384 + vad);
                LDSM4T(v_l, bb + 24576 + vad);
                #pragma unroll
                for (int t = 0; t < 2; t++) {
                    float* d = o[db*2 + t];
                    MMA16816(d, ph[cc], v_h + t*2);
                    MMA16816(d, pl[cc], v_h + t*2);
                    MMA16816(d, ph[cc], v_l + t*2);
                }
            }
        }
    }

    // --- finalize: /l, split-bf16 store to GEMM2 A arrays [B,Ts,D] ---
    float inv0 = 1.0f / l0, inv1 = 1.0f / l1;
    int b = bh >> 4, h = bh & 15;
    int q0g = qblk*64 + wid*16 + r;
    size_t row0 = ((size_t)(b*TS + q0g))*DD + h*HD;
    size_t row1 = row0 + (size_t)8*DD;
    #pragma unroll
    for (int j = 0; j < 8; j++) {
        int dcol = j*8 + 2*c;
        uint32_t H, L;
        pack_split(o[j][0]*inv0, o[j][1]*inv0, H, L);
        *(uint32_t*)(g_a2h + row0 + dcol) = H;
        *(uint32_t*)(g_a2l + row0 + dcol) = L;
        pack_split(o[j][2]*inv1, o[j][3]*inv1, H, L);
        *(uint32_t*)(g_a2h + row1 + dcol) = H;
        *(uint32_t*)(g_a2l + row1 + dcol) = L;
    }
}

// ---------------------------------------------------------------------------
// Linear upsample Ts->T (scale 0.25) + residual add.
// ---------------------------------------------------------------------------
__global__ __launch_bounds__(256) void upsample_kernel(const float* __restrict__ x,
                                                       float* __restrict__ outp)
{
    int gid = blockIdx.x * 256 + threadIdx.x;
    int d4 = gid & 255;
    int t  = (gid >> 8) & (TT - 1);
    int b  = gid >> 20;
    float src = ((float)t + 0.5f) * ((float)TS / (float)TT) - 0.5f;
    src = fminf(fmaxf(src, 0.0f), (float)(TS - 1));
    float fi0 = floorf(src);
    int i0 = (int)fi0;
    int i1 = min(i0 + 1, TS - 1);
    float w  = src - fi0;
    float w0 = 1.0f - w;
    const float4* pr = (const float4*)g_proj;
    float4 p0 = pr[(b*TS + i0)*256 + d4];
    float4 p1 = pr[(b*TS + i1)*256 + d4];
    float4 xv = ((const float4*)x)[gid];
    float4 ov;
    ov.x = xv.x + p0.x*w0 + p1.x*w;
    ov.y = xv.y + p0.y*w0 + p1.y*w;
    ov.z = xv.z + p0.z*w0 + p1.z*w;
    ov.w = xv.w + p0.w*w0 + p1.w*w;
    ((float4*)outp)[gid] = ov;
}

// ---------------------------------------------------------------------------
extern "C" void kernel_launch(void* const* d_in, const int* in_sizes, int n_in,
                              void* d_out, int out_size)
{
    const float* x      = (const float*)d_in[0];
    const float* norm_w = (const float*)d_in[1];
    const float* norm_b = (const float*)d_in[2];
    const float* W_qkv  = (const float*)d_in[3];
    const float* b_qkv  = (const float*)d_in[4];
    const float* W_out  = (const float*)d_in[5];
    const float* b_out  = (const float*)d_in[6];
    float* out = (float*)d_out;

    // Idempotent; called every invocation (no static guards allowed).
    cudaFuncSetAttribute(gemm_mma, cudaFuncAttributeMaxDynamicSharedMemorySize, GSMEM);
    cudaFuncSetAttribute(attn_mma, cudaFuncAttributeMaxDynamicSharedMemorySize, ATT_SMEM);

    float *qkv_p, *proj_p;
    __nv_bfloat16 *a1h, *a1l, *a2h, *a2l, *wqh, *wql, *woh, *wol;
    cudaGetSymbolAddress((void**)&qkv_p,  g_qkv);
    cudaGetSymbolAddress((void**)&proj_p, g_proj);
    cudaGetSymbolAddress((void**)&a1h, g_a1h);
    cudaGetSymbolAddress((void**)&a1l, g_a1l);
    cudaGetSymbolAddress((void**)&a2h, g_a2h);
    cudaGetSymbolAddress((void**)&a2l, g_a2l);
    cudaGetSymbolAddress((void**)&wqh, g_wqh);
    cudaGetSymbolAddress((void**)&wql, g_wql);
    cudaGetSymbolAddress((void**)&woh, g_woh);
    cudaGetSymbolAddress((void**)&wol, g_wol);

    ln_kernel<<<MROWS, 256>>>(x, norm_w, norm_b);
    wsplit<<<dim3(3*DD/32, DD/32), 256>>>(W_qkv, wqh, wql, 3*DD);
    wsplit<<<dim3(DD/32, DD/32), 256>>>(W_out, woh, wol, DD);

    gemm_mma<<<dim3(3*DD/128, MROWS/128), 256, GSMEM>>>(a1h, a1l, wqh, wql,
                                                        b_qkv, qkv_p, 3*DD);
    rope_split<<<(BH*TS*32)/256, 256>>>();
    attn_mma<<<dim3(16, BH), 128, ATT_SMEM>>>();
    gemm_mma<<<dim3(DD/128, MROWS/128), 256, GSMEM>>>(a2h, a2l, woh, wol,
                                                      b_out, proj_p, DD);
    upsample_kernel<<<(BB*TT*DD/4)/256, 256>>>(x, out);
}

// round 14
// speedup vs baseline: 2.6270x; 1.1085x over previous
#include <cuda_runtime.h>
#include <cuda_bf16.h>
#include <math.h>
#include <stdint.h>

// Problem constants
#define BB 4
#define TT 4096
#define DD 1024
#define HH 16
#define HD 64
#define TS 1024
#define MROWS (BB*TS)
#define BH (BB*HH)

// Scratch (allocation-free: __device__ globals)
__device__ float g_qkv[MROWS*3*DD];                          // 48 MB qkv fp32
__device__ float g_proj[MROWS*DD];                           // 16 MB out projection
__device__ __nv_bfloat16 g_a1h[MROWS*DD], g_a1l[MROWS*DD];   // LN rows, split bf16
__device__ __nv_bfloat16 g_a2h[MROWS*DD], g_a2l[MROWS*DD];   // attn out, split bf16
__device__ __nv_bfloat16 g_wqh[3*DD*DD], g_wql[3*DD*DD];     // W_qkv^T split
__device__ __nv_bfloat16 g_woh[DD*DD],  g_wol[DD*DD];        // W_out^T split
// RoPE'd split-bf16 attention operands, [B,H,Ts,64]
__device__ __nv_bfloat16 g_qh[BH*TS*HD], g_ql[BH*TS*HD];
__device__ __nv_bfloat16 g_kh[BH*TS*HD], g_kl[BH*TS*HD];
__device__ __nv_bfloat16 g_vh[BH*TS*HD], g_vl[BH*TS*HD];

__device__ __forceinline__ uint32_t smem_u32(const void* p) {
    uint32_t a;
    asm("{ .reg .u64 t; cvta.to.shared.u64 t, %1; cvt.u32.u64 %0, t; }"
        : "=r"(a) : "l"(p));
    return a;
}
#define SWZ(x) ((x) ^ (((x) >> 3) & 0x70))

#define LDSM4(r, addr) \
    asm volatile("ldmatrix.sync.aligned.m8n8.x4.shared.b16 {%0,%1,%2,%3}, [%4];" \
        : "=r"((r)[0]), "=r"((r)[1]), "=r"((r)[2]), "=r"((r)[3]) : "r"(addr))

#define LDSM4T(r, addr) \
    asm volatile("ldmatrix.sync.aligned.m8n8.x4.trans.shared.b16 {%0,%1,%2,%3}, [%4];" \
        : "=r"((r)[0]), "=r"((r)[1]), "=r"((r)[2]), "=r"((r)[3]) : "r"(addr))

#define MMA16816(d, a, b) \
    asm volatile("mma.sync.aligned.m16n8k16.row.col.f32.bf16.bf16.f32 " \
        "{%0,%1,%2,%3},{%4,%5,%6,%7},{%8,%9},{%0,%1,%2,%3};" \
        : "+f"((d)[0]), "+f"((d)[1]), "+f"((d)[2]), "+f"((d)[3]) \
        : "r"((a)[0]), "r"((a)[1]), "r"((a)[2]), "r"((a)[3]), \
          "r"((b)[0]), "r"((b)[1]))

#define CPA16(dst, src) \
    asm volatile("cp.async.cg.shared.global [%0], [%1], 16;" :: "r"(dst), "l"(src) : "memory")
#define CPA_COMMIT() asm volatile("cp.async.commit_group;" ::: "memory")
#define CPA_WAIT0()  asm volatile("cp.async.wait_group 0;" ::: "memory")
#define CPA_WAIT1()  asm volatile("cp.async.wait_group 1;" ::: "memory")

#define GSMEM 197632     // gemm: 3 x 64KB stages + align slack
#define ATT_SMEM 82944   // attn: 2 x 32KB (K/V hi/lo) + 16KB Q + slack

__device__ __forceinline__ void pack_split(float a, float b, uint32_t& hi, uint32_t& lo) {
    __nv_bfloat162 h = __floats2bfloat162_rn(a, b);
    float ra = a - __bfloat162float(h.x);
    float rb = b - __bfloat162float(h.y);
    __nv_bfloat162 l2 = __floats2bfloat162_rn(ra, rb);
    hi = *(uint32_t*)&h;
    lo = *(uint32_t*)&l2;
}

// ---------------------------------------------------------------------------
// LayerNorm on strided rows -> split-bf16 A1 (hi/lo)
// ---------------------------------------------------------------------------
__global__ __launch_bounds__(256) void ln_kernel(const float* __restrict__ x,
                                                 const float* __restrict__ w,
                                                 const float* __restrict__ bias)
{
    int row = blockIdx.x;
    int b = row >> 10, ts = row & 1023;
    int tid = threadIdx.x;
    const float4* xr = (const float4*)(x + ((size_t)(b*TT + ts*4))*DD);
    float4 v = xr[tid];
    float s  = v.x + v.y + v.z + v.w;
    float sq = v.x*v.x + v.y*v.y + v.z*v.z + v.w*v.w;
    #pragma unroll
    for (int o = 16; o > 0; o >>= 1) {
        s  += __shfl_xor_sync(0xffffffffu, s,  o);
        sq += __shfl_xor_sync(0xffffffffu, sq, o);
    }
    __shared__ float rs[8], rq[8];
    int wid = tid >> 5, lane = tid & 31;
    if (lane == 0) { rs[wid] = s; rq[wid] = sq; }
    __syncthreads();
    if (tid == 0) {
        float S = 0.f, Q = 0.f;
        #pragma unroll
        for (int i = 0; i < 8; i++) { S += rs[i]; Q += rq[i]; }
        rs[0] = S; rq[0] = Q;
    }
    __syncthreads();
    float mean = rs[0] * (1.0f/DD);
    float var  = rq[0] * (1.0f/DD) - mean*mean;
    float rstd = rsqrtf(var + 1e-5f);
    float4 wv = ((const float4*)w)[tid];
    float4 bv = ((const float4*)bias)[tid];
    float vals[4];
    vals[0] = (v.x - mean)*rstd*wv.x + bv.x;
    vals[1] = (v.y - mean)*rstd*wv.y + bv.y;
    vals[2] = (v.z - mean)*rstd*wv.z + bv.z;
    vals[3] = (v.w - mean)*rstd*wv.w + bv.w;
    size_t base = (size_t)row*DD + tid*4;
    #pragma unroll
    for (int j = 0; j < 4; j += 2) {
        uint32_t H, L;
        pack_split(vals[j], vals[j+1], H, L);
        *(uint32_t*)(g_a1h + base + j) = H;
        *(uint32_t*)(g_a1l + base + j) = L;
    }
}

// ---------------------------------------------------------------------------
// Weight transpose + split: W[K=1024][N] fp32 -> T[N][1024] bf16 hi/lo
// ---------------------------------------------------------------------------
__global__ __launch_bounds__(256) void wsplit(const float* __restrict__ W,
                                              __nv_bfloat16* __restrict__ Th,
                                              __nv_bfloat16* __restrict__ Tl,
                                              int N)
{
    __shared__ float t[32][33];
    int n0 = blockIdx.x*32, k0 = blockIdx.y*32;
    int tx = threadIdx.x & 31, ty = threadIdx.x >> 5;
    #pragma unroll
    for (int i = 0; i < 4; i++)
        t[ty + i*8][tx] = W[(size_t)(k0 + ty + i*8)*N + n0 + tx];
    __syncthreads();
    #pragma unroll
    for (int i = 0; i < 4; i++) {
        int n = n0 + ty + i*8, k = k0 + tx;
        float v = t[tx][ty + i*8];
        __nv_bfloat16 h = __float2bfloat16(v);
        __nv_bfloat16 l = __float2bfloat16(v - __bfloat162float(h));
        Th[(size_t)n*DD + k] = h;
        Tl[(size_t)n*DD + k] = l;
    }
}

// ---------------------------------------------------------------------------
// mma.sync split-bf16 GEMM v2: C = A @ B^T + bias.
// Tile 128x128, 16 warps (4m x 4n, 32x32 each), K-chunk 64,
// 3-stage cp.async pipeline with wait_group 1.
// ---------------------------------------------------------------------------
__global__ __launch_bounds__(512, 1)
void gemm_mma(const __nv_bfloat16* __restrict__ Ah, const __nv_bfloat16* __restrict__ Al,
              const __nv_bfloat16* __restrict__ Bh, const __nv_bfloat16* __restrict__ Bl,
              const float* __restrict__ bias, float* __restrict__ C, int ldc)
{
    extern __shared__ char dsm[];
    uint32_t sb = (smem_u32(dsm) + 1023) & ~1023u;
    int tid = threadIdx.x, lane = tid & 31, wid = tid >> 5;
    int bn = blockIdx.x*128, bm = blockIdx.y*128;
    int m0 = (wid & 3)*32, n0 = (wid >> 2)*32;

    // gmem->smem copy mapping: row = tid/4, 32B quarter-row per array
    int row = tid >> 2, q = tid & 3;
    const uint4* gsrc[4] = {
        (const uint4*)(Ah + (size_t)(bm+row)*DD) + q*2,
        (const uint4*)(Al + (size_t)(bm+row)*DD) + q*2,
        (const uint4*)(Bh + (size_t)(bn+row)*DD) + q*2,
        (const uint4*)(Bl + (size_t)(bn+row)*DD) + q*2 };
    uint32_t so = (uint32_t)(row*128 + q*32);

    float acc[2][4][4];
    #pragma unroll
    for (int i = 0; i < 2; i++)
        #pragma unroll
        for (int j = 0; j < 4; j++)
            #pragma unroll
            for (int k = 0; k < 4; k++) acc[i][j][k] = 0.f;

    auto copy_chunk = [&](int c, int buf) {
        uint32_t bbase = sb + buf*65536;
        #pragma unroll
        for (int a = 0; a < 4; a++) {
            const uint4* src = gsrc[a] + c*8;
            uint32_t dst = bbase + a*16384;
            CPA16(dst + SWZ(so),      src);
            CPA16(dst + SWZ(so + 16), src + 1);
        }
        CPA_COMMIT();
    };

    copy_chunk(0, 0);
    copy_chunk(1, 1);

    for (int c = 0; c < 16; c++) {
        CPA_WAIT1();               // chunk c arrived (c+1 may be in flight)
        __syncthreads();           // all warps done computing chunk c-1
        if (c + 2 < 16) copy_chunk(c + 2, (c + 2) % 3);

        uint32_t bbase = sb + (c % 3)*65536;
        #pragma unroll
        for (int ks = 0; ks < 4; ks++) {
            uint32_t a_h[2][4], a_l[2][4];
            #pragma unroll
            for (int mi = 0; mi < 2; mi++) {
                int r  = m0 + mi*16 + (lane & 15);
                int kb = ks*16 + (lane >> 4)*8;
                uint32_t ad = SWZ((uint32_t)(r*128 + kb*2));
                LDSM4(a_h[mi], bbase + ad);
                LDSM4(a_l[mi], bbase + 16384 + ad);
            }
            #pragma unroll
            for (int nj = 0; nj < 2; nj++) {
                int rn = n0 + nj*16 + (lane & 7) + ((lane >> 4) & 1)*8;
                int kb = ks*16 + ((lane >> 3) & 1)*8;
                uint32_t ad = SWZ((uint32_t)(rn*128 + kb*2));
                uint32_t b_h[4], b_l[4];
                LDSM4(b_h, bbase + 32768 + ad);
                LDSM4(b_l, bbase + 49152 + ad);
                #pragma unroll
                for (int mi = 0; mi < 2; mi++) {
                    #pragma unroll
                    for (int t = 0; t < 2; t++) {
                        float* d = acc[mi][nj*2 + t];
                        MMA16816(d, a_h[mi], b_h + t*2);
                        MMA16816(d, a_h[mi], b_l + t*2);
                        MMA16816(d, a_l[mi], b_h + t*2);
                    }
                }
            }
        }
    }

    // Epilogue: registers -> gmem with bias
    #pragma unroll
    for (int mi = 0; mi < 2; mi++) {
        int r0 = bm + m0 + mi*16 + (lane >> 2);
        #pragma unroll
        for (int nt = 0; nt < 4; nt++) {
            int col = bn + n0 + nt*8 + (lane & 3)*2;
            float2 bv = *(const float2*)(bias + col);
            float2 v0, v1;
            v0.x = acc[mi][nt][0] + bv.x; v0.y = acc[mi][nt][1] + bv.y;
            v1.x = acc[mi][nt][2] + bv.x; v1.y = acc[mi][nt][3] + bv.y;
            *(float2*)(C + (size_t)r0*ldc + col)     = v0;
            *(float2*)(C + (size_t)(r0+8)*ldc + col) = v1;
        }
    }
}

// ---------------------------------------------------------------------------
// RoPE + split-bf16 conversion: g_qkv fp32 -> Q(,*0.125)/K/V split [B,H,Ts,64]
// ---------------------------------------------------------------------------
__global__ __launch_bounds__(256) void rope_split()
{
    int idx = blockIdx.x * 256 + threadIdx.x;   // BH*TS*32
    int i  = idx & 31;
    int h  = (idx >> 5) & 15;
    int ts = (idx >> 9) & 1023;
    int b  = idx >> 19;
    float freq = expf(-(float)(2*i) * (9.210340371976184f / 64.0f));
    float ang = (float)ts * freq;
    float sn, cs;
    sincosf(ang, &sn, &cs);
    size_t src = ((size_t)(b*TS + ts))*3*DD + h*HD;
    float q0 = g_qkv[src+i],      q1 = g_qkv[src+i+32];
    float k0 = g_qkv[src+DD+i],   k1 = g_qkv[src+DD+i+32];
    float v0 = g_qkv[src+2*DD+i], v1 = g_qkv[src+2*DD+i+32];
    float qr0 = (q0*cs - q1*sn) * 0.125f;
    float qr1 = (q1*cs + q0*sn) * 0.125f;
    float kr0 = k0*cs - k1*sn;
    float kr1 = k1*cs + k0*sn;
    size_t dst = ((size_t)((b*HH + h)*TS + ts))*HD;
    __nv_bfloat16 t;
    t = __float2bfloat16(qr0); g_qh[dst+i]    = t; g_ql[dst+i]    = __float2bfloat16(qr0 - __bfloat162float(t));
    t = __float2bfloat16(qr1); g_qh[dst+i+32] = t; g_ql[dst+i+32] = __float2bfloat16(qr1 - __bfloat162float(t));
    t = __float2bfloat16(kr0); g_kh[dst+i]    = t; g_kl[dst+i]    = __float2bfloat16(kr0 - __bfloat162float(t));
    t = __float2bfloat16(kr1); g_kh[dst+i+32] = t; g_kl[dst+i+32] = __float2bfloat16(kr1 - __bfloat162float(t));
    t = __float2bfloat16(v0);  g_vh[dst+i]    = t; g_vl[dst+i]    = __float2bfloat16(v0 - __bfloat162float(t));
    t = __float2bfloat16(v1);  g_vh[dst+i+32] = t; g_vl[dst+i+32] = __float2bfloat16(v1 - __bfloat162float(t));
}

// ---------------------------------------------------------------------------
// Causal flash attention on mma.sync (validated round 11).
// ---------------------------------------------------------------------------
__global__ __launch_bounds__(128, 1) void attn_mma()
{
    extern __shared__ char dsm[];
    uint32_t sb = (smem_u32(dsm) + 1023) & ~1023u;
    int tid = threadIdx.x, lane = tid & 31, wid = tid >> 5;
    int qblk = 15 - blockIdx.x;
    int bh   = blockIdx.y;
    size_t head = (size_t)bh*TS*HD;

    const uint32_t QH = sb + 65536, QL = QH + 8192;
    int crow = tid >> 1, chalf = tid & 1;
    uint32_t cso = (uint32_t)(crow*128 + chalf*64);

    auto load_tile = [&](int kt, int s) {
        uint32_t bb = sb + s*32768;
        size_t src = head + (size_t)(kt*64 + crow)*HD + chalf*32;
        const uint4* pk_h = (const uint4*)(g_kh + src);
        const uint4* pk_l = (const uint4*)(g_kl + src);
        const uint4* pv_h = (const uint4*)(g_vh + src);
        const uint4* pv_l = (const uint4*)(g_vl + src);
        #pragma unroll
        for (int i = 0; i < 4; i++) {
            uint32_t sw = SWZ(cso + i*16);
            CPA16(bb + sw,         pk_h + i);
            CPA16(bb +  8192 + sw, pk_l + i);
            CPA16(bb + 16384 + sw, pv_h + i);
            CPA16(bb + 24576 + sw, pv_l + i);
        }
        CPA_COMMIT();
    };
    load_tile(0, 0);

    {
        size_t qsrc = head + (size_t)(qblk*64 + crow)*HD + chalf*32;
        #pragma unroll
        for (int i = 0; i < 4; i++) {
            uint32_t sw = SWZ(cso + i*16);
            *(uint4*)(dsm + (QH - smem_u32(dsm)) + sw) = *(const uint4*)(g_qh + qsrc + i*8);
            *(uint4*)(dsm + (QL - smem_u32(dsm)) + sw) = *(const uint4*)(g_ql + qsrc + i*8);
        }
    }

    float o[8][4];
    #pragma unroll
    for (int j = 0; j < 8; j++)
        #pragma unroll
        for (int k = 0; k < 4; k++) o[j][k] = 0.f;
    float m0 = -1e30f, m1 = -1e30f, l0 = 0.f, l1 = 0.f;
    int r = lane >> 2, c = lane & 3;

    for (int kt = 0; kt <= qblk; kt++) {
        CPA_WAIT0();
        __syncthreads();
        if (kt < qblk) load_tile(kt + 1, (kt + 1) & 1);
        uint32_t bb = sb + (kt & 1)*32768;

        float s[8][4];
        #pragma unroll
        for (int j = 0; j < 8; j++)
            #pragma unroll
            for (int k = 0; k < 4; k++) s[j][k] = 0.f;

        #pragma unroll
        for (int ks = 0; ks < 4; ks++) {
            uint32_t aq = SWZ((uint32_t)((wid*16 + (lane & 15))*128 + (ks*16 + 8*(lane >> 4))*2));
            uint32_t a_h[4], a_l[4];
            LDSM4(a_h, QH + aq);
            LDSM4(a_l, QL + aq);
            #pragma unroll
            for (int nj = 0; nj < 4; nj++) {
                uint32_t bad = SWZ((uint32_t)((nj*16 + (lane & 7) + ((lane >> 4) & 1)*8)*128
                                              + (ks*16 + ((lane >> 3) & 1)*8)*2));
                uint32_t b_h[4], b_l[4];
                LDSM4(b_h, bb + bad);
                LDSM4(b_l, bb + 8192 + bad);
                #pragma unroll
                for (int t = 0; t < 2; t++) {
                    float* d = s[nj*2 + t];
                    MMA16816(d, a_h, b_h + t*2);
                    MMA16816(d, a_h, b_l + t*2);
                    MMA16816(d, a_l, b_h + t*2);
                }
            }
        }

        if (kt == qblk) {
            int row0 = wid*16 + r, row1 = row0 + 8;
            #pragma unroll
            for (int j = 0; j < 8; j++) {
                int col = j*8 + 2*c;
                if (col     > row0) s[j][0] = -1e30f;
                if (col + 1 > row0) s[j][1] = -1e30f;
                if (col     > row1) s[j][2] = -1e30f;
                if (col + 1 > row1) s[j][3] = -1e30f;
            }
        }

        float mx0 = -1e30f, mx1 = -1e30f;
        #pragma unroll
        for (int j = 0; j < 8; j++) {
            mx0 = fmaxf(mx0, fmaxf(s[j][0], s[j][1]));
            mx1 = fmaxf(mx1, fmaxf(s[j][2], s[j][3]));
        }
        mx0 = fmaxf(mx0, __shfl_xor_sync(0xffffffffu, mx0, 1));
        mx0 = fmaxf(mx0, __shfl_xor_sync(0xffffffffu, mx0, 2));
        mx1 = fmaxf(mx1, __shfl_xor_sync(0xffffffffu, mx1, 1));
        mx1 = fmaxf(mx1, __shfl_xor_sync(0xffffffffu, mx1, 2));
        float mn0 = fmaxf(m0, mx0), mn1 = fmaxf(m1, mx1);
        float al0 = __expf(m0 - mn0), al1 = __expf(m1 - mn1);
        m0 = mn0; m1 = mn1;
        float sum0 = 0.f, sum1 = 0.f;
        #pragma unroll
        for (int j = 0; j < 8; j++) {
            s[j][0] = __expf(s[j][0] - mn0); sum0 += s[j][0];
            s[j][1] = __expf(s[j][1] - mn0); sum0 += s[j][1];
            s[j][2] = __expf(s[j][2] - mn1); sum1 += s[j][2];
            s[j][3] = __expf(s[j][3] - mn1); sum1 += s[j][3];
        }
        sum0 += __shfl_xor_sync(0xffffffffu, sum0, 1);
        sum0 += __shfl_xor_sync(0xffffffffu, sum0, 2);
        sum1 += __shfl_xor_sync(0xffffffffu, sum1, 1);
        sum1 += __shfl_xor_sync(0xffffffffu, sum1, 2);
        l0 = l0*al0 + sum0;
        l1 = l1*al1 + sum1;
        #pragma unroll
        for (int j = 0; j < 8; j++) {
            o[j][0] *= al0; o[j][1] *= al0;
            o[j][2] *= al1; o[j][3] *= al1;
        }

        uint32_t ph[4][4], pl[4][4];
        #pragma unroll
        for (int cc = 0; cc < 4; cc++) {
            int j = 2*cc;
            pack_split(s[j][0],   s[j][1],   ph[cc][0], pl[cc][0]);
            pack_split(s[j][2],   s[j][3],   ph[cc][1], pl[cc][1]);
            pack_split(s[j+1][0], s[j+1][1], ph[cc][2], pl[cc][2]);
            pack_split(s[j+1][2], s[j+1][3], ph[cc][3], pl[cc][3]);
        }

        #pragma unroll
        for (int cc = 0; cc < 4; cc++) {
            #pragma unroll
            for (int db = 0; db < 4; db++) {
                uint32_t vad = SWZ((uint32_t)((cc*16 + (lane & 15))*128
                                              + (db*16 + 8*(lane >> 4))*2));
                uint32_t v_h[4], v_l[4];
                LDSM4T(v_h, bb + 16384 + vad);
                LDSM4T(v_l, bb + 24576 + vad);
                #pragma unroll
                for (int t = 0; t < 2; t++) {
                    float* d = o[db*2 + t];
                    MMA16816(d, ph[cc], v_h + t*2);
                    MMA16816(d, pl[cc], v_h + t*2);
                    MMA16816(d, ph[cc], v_l + t*2);
                }
            }
        }
    }

    float inv0 = 1.0f / l0, inv1 = 1.0f / l1;
    int b = bh >> 4, h = bh & 15;
    int q0g = qblk*64 + wid*16 + r;
    size_t row0 = ((size_t)(b*TS + q0g))*DD + h*HD;
    size_t row1 = row0 + (size_t)8*DD;
    #pragma unroll
    for (int j = 0; j < 8; j++) {
        int dcol = j*8 + 2*c;
        uint32_t H, L;
        pack_split(o[j][0]*inv0, o[j][1]*inv0, H, L);
        *(uint32_t*)(g_a2h + row0 + dcol) = H;
        *(uint32_t*)(g_a2l + row0 + dcol) = L;
        pack_split(o[j][2]*inv1, o[j][3]*inv1, H, L);
        *(uint32_t*)(g_a2h + row1 + dcol) = H;
        *(uint32_t*)(g_a2l + row1 + dcol) = L;
    }
}

// ---------------------------------------------------------------------------
// Linear upsample Ts->T (scale 0.25) + residual add.
// ---------------------------------------------------------------------------
__global__ __launch_bounds__(256) void upsample_kernel(const float* __restrict__ x,
                                                       float* __restrict__ outp)
{
    int gid = blockIdx.x * 256 + threadIdx.x;
    int d4 = gid & 255;
    int t  = (gid >> 8) & (TT - 1);
    int b  = gid >> 20;
    float src = ((float)t + 0.5f) * ((float)TS / (float)TT) - 0.5f;
    src = fminf(fmaxf(src, 0.0f), (float)(TS - 1));
    float fi0 = floorf(src);
    int i0 = (int)fi0;
    int i1 = min(i0 + 1, TS - 1);
    float w  = src - fi0;
    float w0 = 1.0f - w;
    const float4* pr = (const float4*)g_proj;
    float4 p0 = pr[(b*TS + i0)*256 + d4];
    float4 p1 = pr[(b*TS + i1)*256 + d4];
    float4 xv = ((const float4*)x)[gid];
    float4 ov;
    ov.x = xv.x + p0.x*w0 + p1.x*w;
    ov.y = xv.y + p0.y*w0 + p1.y*w;
    ov.z = xv.z + p0.z*w0 + p1.z*w;
    ov.w = xv.w + p0.w*w0 + p1.w*w;
    ((float4*)outp)[gid] = ov;
}

// ---------------------------------------------------------------------------
extern "C" void kernel_launch(void* const* d_in, const int* in_sizes, int n_in,
                              void* d_out, int out_size)
{
    const float* x      = (const float*)d_in[0];
    const float* norm_w = (const float*)d_in[1];
    const float* norm_b = (const float*)d_in[2];
    const float* W_qkv  = (const float*)d_in[3];
    const float* b_qkv  = (const float*)d_in[4];
    const float* W_out  = (const float*)d_in[5];
    const float* b_out  = (const float*)d_in[6];
    float* out = (float*)d_out;

    cudaFuncSetAttribute(gemm_mma, cudaFuncAttributeMaxDynamicSharedMemorySize, GSMEM);
    cudaFuncSetAttribute(attn_mma, cudaFuncAttributeMaxDynamicSharedMemorySize, ATT_SMEM);

    float *qkv_p, *proj_p;
    __nv_bfloat16 *a1h, *a1l, *a2h, *a2l, *wqh, *wql, *woh, *wol;
    cudaGetSymbolAddress((void**)&qkv_p,  g_qkv);
    cudaGetSymbolAddress((void**)&proj_p, g_proj);
    cudaGetSymbolAddress((void**)&a1h, g_a1h);
    cudaGetSymbolAddress((void**)&a1l, g_a1l);
    cudaGetSymbolAddress((void**)&a2h, g_a2h);
    cudaGetSymbolAddress((void**)&a2l, g_a2l);
    cudaGetSymbolAddress((void**)&wqh, g_wqh);
    cudaGetSymbolAddress((void**)&wql, g_wql);
    cudaGetSymbolAddress((void**)&woh, g_woh);
    cudaGetSymbolAddress((void**)&wol, g_wol);

    ln_kernel<<<MROWS, 256>>>(x, norm_w, norm_b);
    wsplit<<<dim3(3*DD/32, DD/32), 256>>>(W_qkv, wqh, wql, 3*DD);
    wsplit<<<dim3(DD/32, DD/32), 256>>>(W_out, woh, wol, DD);

    gemm_mma<<<dim3(3*DD/128, MROWS/128), 512, GSMEM>>>(a1h, a1l, wqh, wql,
                                                        b_qkv, qkv_p, 3*DD);
    rope_split<<<(BH*TS*32)/256, 256>>>();
    attn_mma<<<dim3(16, BH), 128, ATT_SMEM>>>();
    gemm_mma<<<dim3(DD/128, MROWS/128), 512, GSMEM>>>(a2h, a2l, woh, wol,
                                                      b_out, proj_p, DD);
    upsample_kernel<<<(BB*TT*DD/4)/256, 256>>>(x, out);
}